// round 7
// baseline (speedup 1.0000x reference)
#include <cuda_runtime.h>
#include <cstdint>

// B=256, N=256. Greedy masked argmax (exact reference semantics: max value,
// tie -> smallest flat index). Keys = fp32 bit patterns; softmax values are in
// (0,1) => positive and < 1.0f, so bits are order-monotone uint32 and < 2^30.
// Slot state packed in one u64:  h = (key << 16) | (~((row<<8)|col) & 0xFFFF)
// so u64 max = lexicographic (max key, min flat index). 0 = dead/invalid.
//
// Kernel 1 (parallel): per-row exact top-2 -> g_head / g_back scratch.
// Kernel 2 (1 warp/batch, serial): greedy loop with register head+backup,
// eager backup invalidation, exact promotion, rare cooperative rescans
// (with top-2 refill), fused zero+one-hot output.

#define NN 256
#define FULL 0xFFFFFFFFu
typedef unsigned long long u64;

__device__ u64 g_head[256 * NN];
__device__ u64 g_back[256 * NN];

__device__ __forceinline__ u64 pairmax(u64 a, u64 b) { return a > b ? a : b; }

__device__ __forceinline__ u64 packhc(unsigned key, int row, int col) {
    unsigned pk = (unsigned)((row << 8) | col);
    return ((u64)key << 16) | (u64)((~pk) & 0xFFFFu);
}

// ---------------- kernel 1: parallel per-row top-2 init ----------------
__global__ __launch_bounds__(256)
void init_kernel(const float* __restrict__ scores) {
    const int b = blockIdx.x;
    const int warp = threadIdx.x >> 5;
    const int lane = threadIdx.x & 31;
    const float* base = scores + (size_t)b * NN * NN;

    #pragma unroll 1
    for (int rg = 0; rg < 8; rg++) {          // 8 groups of 4 rows per warp
        const int row0 = warp * 32 + rg * 4;
        float4 A[4], Bq[4];
        #pragma unroll
        for (int q = 0; q < 4; q++) {
            const float4* rp = (const float4*)(base + (size_t)(row0 + q) * NN);
            A[q]  = __ldg(rp + lane);
            Bq[q] = __ldg(rp + 32 + lane);
        }
        #pragma unroll
        for (int q = 0; q < 4; q++) {
            const int row = row0 + q;
            unsigned k1 = 0u, k2 = 0u; int c1 = 0, c2 = 0;
            const int c0 = 4 * lane;
            float va[8] = {A[q].x, A[q].y, A[q].z, A[q].w,
                           Bq[q].x, Bq[q].y, Bq[q].z, Bq[q].w};
            #pragma unroll
            for (int i = 0; i < 8; i++) {
                const unsigned key = __float_as_uint(va[i]);
                const int col = (i < 4) ? (c0 + i) : (128 + c0 + (i - 4));
                if (key > k1)      { k2 = k1; c2 = c1; k1 = key; c1 = col; }
                else if (key > k2) { k2 = key; c2 = col; }
            }
            const unsigned m1 = __reduce_max_sync(FULL, k1);
            const unsigned p1 = __reduce_min_sync(FULL, (k1 == m1) ? (unsigned)c1 : FULL);
            const bool win = (k1 == m1) && ((unsigned)c1 == p1);
            const unsigned sk = win ? k2 : k1;
            const unsigned sc = win ? (unsigned)c2 : (unsigned)c1;
            const unsigned m2 = __reduce_max_sync(FULL, sk);
            const unsigned p2 = __reduce_min_sync(FULL, (sk == m2) ? sc : FULL);
            if (lane == 0) {
                g_head[b * NN + row] = packhc(m1, row, (int)p1);
                g_back[b * NN + row] = m2 ? packhc(m2, row, (int)p2) : 0ull;
            }
        }
    }
}

// ---------------- kernel 2: serial greedy loop, 1 warp per batch ----------------
__global__ __launch_bounds__(32)
void greedy_perm_kernel(const float* __restrict__ scores, float* __restrict__ out) {
    __shared__ int s_perm[NN];

    const int b = blockIdx.x;
    const int lane = threadIdx.x;
    const float* base = scores + (size_t)b * NN * NN;
    float* obase = out + (size_t)b * NN * NN;

    u64 h[8], bb[8];
    unsigned cmask[8];
    #pragma unroll
    for (int k = 0; k < 8; k++) cmask[k] = 0u;
    #pragma unroll
    for (int j = 0; j < 8; j++) {
        h[j]  = __ldg(&g_head[b * NN + j * 32 + lane]);
        bb[j] = __ldg(&g_back[b * NN + j * 32 + lane]);
    }

    #pragma unroll 1
    for (int it = 0; it < NN; it++) {
        // local lexicographic max over 8 owned slots (pure ALU tree)
        u64 loc = pairmax(pairmax(pairmax(h[0], h[1]), pairmax(h[2], h[3])),
                          pairmax(pairmax(h[4], h[5]), pairmax(h[6], h[7])));
        const unsigned bk = (unsigned)(loc >> 16);            // 30-bit key
        const unsigned cp = (~(unsigned)loc) & 0xFFFFu;       // packed (row<<8|col)

        const unsigned m   = __reduce_max_sync(FULL, bk);
        const unsigned sel = __reduce_min_sync(FULL, (bk == m) ? cp : FULL);
        const int r = (int)(sel >> 8);
        const int c = (int)(sel & 255u);

        if (lane == 0) s_perm[r] = c;

        // mask col c (replicated, static indexing)
        {
            const int w = c >> 5; const unsigned bit = 1u << (c & 31);
            #pragma unroll
            for (int k = 0; k < 8; k++) if (k == w) cmask[k] |= bit;
        }
        // kill assigned row
        if (lane == (r & 31)) {
            const int slot = r >> 5;
            #pragma unroll
            for (int j = 0; j < 8; j++) if (j == slot) { h[j] = 0ull; bb[j] = 0ull; }
        }

        if (it == NN - 1) break;

        // eager backup invalidation, exact promotion, collect rescans
        unsigned need = 0u;
        #pragma unroll
        for (int j = 0; j < 8; j++) {
            if (bb[j] != 0ull && (((~(unsigned)bb[j]) & 255u) == (unsigned)c))
                bb[j] = 0ull;
            if ((h[j] >> 16) != 0ull && (((~(unsigned)h[j]) & 255u) == (unsigned)c)) {
                if (bb[j] != 0ull) { h[j] = bb[j]; bb[j] = 0ull; }
                else               need |= (1u << j);
            }
        }

        unsigned ln = __ballot_sync(FULL, need != 0u);
        while (ln) {
            const int src = __ffs(ln) - 1; ln &= ln - 1;
            unsigned em = __shfl_sync(FULL, need, src);
            while (em) {
                const int jd = __ffs(em) - 1; em &= em - 1;
                const int row = jd * 32 + src;
                const float* rp = base + (size_t)row * NN;
                unsigned k1 = 0u, k2 = 0u; int c1 = 0, c2 = 0;
                #pragma unroll
                for (int k = 0; k < 8; k++) {
                    const int col = k * 32 + lane;
                    const float v = __ldg(rp + col);
                    const unsigned key = ((cmask[k] >> lane) & 1u) ? 0u : __float_as_uint(v);
                    if (key > k1)      { k2 = k1; c2 = c1; k1 = key; c1 = col; }
                    else if (key > k2) { k2 = key; c2 = col; }
                }
                const unsigned m1 = __reduce_max_sync(FULL, k1);
                const unsigned p1 = __reduce_min_sync(FULL, (k1 == m1) ? (unsigned)c1 : FULL);
                const bool win = (k1 == m1) && ((unsigned)c1 == p1);
                const unsigned sk = win ? k2 : k1;
                const unsigned sc = win ? (unsigned)c2 : (unsigned)c1;
                const unsigned m2 = __reduce_max_sync(FULL, sk);
                const unsigned p2 = __reduce_min_sync(FULL, (sk == m2) ? sc : FULL);
                if (lane == src) {
                    #pragma unroll
                    for (int j = 0; j < 8; j++)
                        if (j == jd) {
                            h[j]  = packhc(m1, row, (int)p1);
                            bb[j] = m2 ? packhc(m2, row, (int)p2) : 0ull;
                        }
                }
            }
        }
    }

    __syncwarp();

    // fused output: zeros + one-hot, coalesced float4
    #pragma unroll 4
    for (int row = 0; row < NN; row++) {
        const int pc = s_perm[row];  // broadcast LDS
        float4* op = (float4*)(obase + (size_t)row * NN);
        #pragma unroll
        for (int hh = 0; hh < 2; hh++) {
            const int f4 = lane + 32 * hh;
            const int c0 = 4 * f4;
            float4 vv;
            vv.x = (pc == c0 + 0) ? 1.0f : 0.0f;
            vv.y = (pc == c0 + 1) ? 1.0f : 0.0f;
            vv.z = (pc == c0 + 2) ? 1.0f : 0.0f;
            vv.w = (pc == c0 + 3) ? 1.0f : 0.0f;
            op[f4] = vv;
        }
    }
}

extern "C" void kernel_launch(void* const* d_in, const int* in_sizes, int n_in,
                              void* d_out, int out_size) {
    const float* soft = (const float*)d_in[0];
    float* out = (float*)d_out;
    init_kernel<<<256, 256>>>(soft);
    greedy_perm_kernel<<<256, 32>>>(soft, out);
}

// round 8
// speedup vs baseline: 1.8166x; 1.8166x over previous
#include <cuda_runtime.h>
#include <cstdint>

// B=256, N=256. Greedy masked argmax (exact reference semantics: max value,
// tie -> smallest flat index). Keys = fp32 bit patterns; softmax values are in
// (0,1) => positive, < 1.0f => order-monotone uint32, < 2^30.
// Slot state: one u64  h = (key << 16) | (~((row<<8)|col) & 0xFFFF);
// u64 max == lexicographic (max key, min flat index). 0 = dead.
//
// One CTA per batch, 256 threads:
//   - 8 warps: parallel per-row argmax init (coalesced, warms L1) -> s_h
//   - warp 0: serial greedy loop (R6-winner body: u64 tree + 2 REDUX,
//             eager rescans from L1-warm scores, single combined ballot)
//   - warps 1-7: concurrently zero-fill this batch's 64KB*4 output
//   - after barrier: each thread writes its row's single 1.0

#define NN 256
#define FULL 0xFFFFFFFFu
typedef unsigned long long u64;

__device__ __forceinline__ u64 pairmax(u64 a, u64 b) { return a > b ? a : b; }

__global__ __launch_bounds__(256)
void greedy_perm_kernel(const float* __restrict__ scores, float* __restrict__ out) {
    __shared__ u64 s_h[NN];    // packed head per row
    __shared__ int s_perm[NN];

    const int b    = blockIdx.x;
    const int tid  = threadIdx.x;
    const int warp = tid >> 5;
    const int lane = tid & 31;
    const float* base  = scores + (size_t)b * NN * NN;
    float*       obase = out    + (size_t)b * NN * NN;

    // ---------- parallel init: warp w -> rows w*32 .. w*32+31 ----------
    #pragma unroll 1
    for (int rg = 0; rg < 8; rg++) {
        const int row0 = warp * 32 + rg * 4;
        float4 A[4], Bq[4];
        #pragma unroll
        for (int q = 0; q < 4; q++) {
            const float4* rp = (const float4*)(base + (size_t)(row0 + q) * NN);
            A[q]  = __ldg(rp + lane);
            Bq[q] = __ldg(rp + 32 + lane);
        }
        #pragma unroll
        for (int q = 0; q < 4; q++) {
            const int row = row0 + q;
            const int c0 = 4 * lane;
            u64 w[8];
            w[0] = ((u64)__float_as_uint(A[q].x)  << 32) | (unsigned)~(c0 + 0);
            w[1] = ((u64)__float_as_uint(A[q].y)  << 32) | (unsigned)~(c0 + 1);
            w[2] = ((u64)__float_as_uint(A[q].z)  << 32) | (unsigned)~(c0 + 2);
            w[3] = ((u64)__float_as_uint(A[q].w)  << 32) | (unsigned)~(c0 + 3);
            w[4] = ((u64)__float_as_uint(Bq[q].x) << 32) | (unsigned)~(128 + c0 + 0);
            w[5] = ((u64)__float_as_uint(Bq[q].y) << 32) | (unsigned)~(128 + c0 + 1);
            w[6] = ((u64)__float_as_uint(Bq[q].z) << 32) | (unsigned)~(128 + c0 + 2);
            w[7] = ((u64)__float_as_uint(Bq[q].w) << 32) | (unsigned)~(128 + c0 + 3);
            u64 loc = pairmax(pairmax(pairmax(w[0], w[1]), pairmax(w[2], w[3])),
                              pairmax(pairmax(w[4], w[5]), pairmax(w[6], w[7])));
            const unsigned k1 = (unsigned)(loc >> 32);
            const unsigned c1 = (~(unsigned)loc) & 255u;
            const unsigned m1 = __reduce_max_sync(FULL, k1);
            const unsigned p1 = __reduce_min_sync(FULL, (k1 == m1) ? c1 : FULL);
            if (lane == 0)
                s_h[row] = ((u64)m1 << 16) |
                           (u64)((~(unsigned)((row << 8) | (int)p1)) & 0xFFFFu);
        }
    }
    __syncthreads();

    if (warp == 0) {
        // ---------- serial greedy loop (R6 winner body) ----------
        u64 h[8];
        unsigned cmask[8];
        #pragma unroll
        for (int k = 0; k < 8; k++) cmask[k] = 0u;
        #pragma unroll
        for (int j = 0; j < 8; j++) h[j] = s_h[j * 32 + lane];

        #pragma unroll 1
        for (int it = 0; it < NN; it++) {
            u64 loc = pairmax(pairmax(pairmax(h[0], h[1]), pairmax(h[2], h[3])),
                              pairmax(pairmax(h[4], h[5]), pairmax(h[6], h[7])));
            const unsigned bk = (unsigned)(loc >> 16);       // 30-bit key
            const unsigned cp = (~(unsigned)loc) & 0xFFFFu;  // (row<<8)|col

            const unsigned m   = __reduce_max_sync(FULL, bk);
            const unsigned sel = __reduce_min_sync(FULL, (bk == m) ? cp : FULL);
            const int r = (int)(sel >> 8);
            const int c = (int)(sel & 255u);

            if (lane == 0) s_perm[r] = c;

            // mask col c (replicated, static indexing)
            {
                const int w2 = c >> 5; const unsigned bit = 1u << (c & 31);
                #pragma unroll
                for (int k = 0; k < 8; k++) if (k == w2) cmask[k] |= bit;
            }
            // kill assigned row
            if (lane == (r & 31)) {
                const int slot = r >> 5;
                #pragma unroll
                for (int j = 0; j < 8; j++) if (j == slot) h[j] = 0ull;
            }

            if (it == NN - 1) break;

            // rows whose cached argmax col just got masked -> eager rescan
            unsigned need = 0u;
            #pragma unroll
            for (int j = 0; j < 8; j++)
                if ((unsigned)(h[j] >> 16) != 0u &&
                    (((~(unsigned)h[j]) & 255u) == (unsigned)c))
                    need |= (1u << j);

            unsigned ln = __ballot_sync(FULL, need != 0u);
            while (ln) {
                const int src = __ffs(ln) - 1; ln &= ln - 1;
                unsigned em = __shfl_sync(FULL, need, src);
                while (em) {
                    const int jd = __ffs(em) - 1; em &= em - 1;
                    const int row = jd * 32 + src;
                    const float* rp = base + (size_t)row * NN;
                    u64 w[8];
                    #pragma unroll
                    for (int k = 0; k < 8; k++) {
                        const float v = __ldg(rp + k * 32 + lane);
                        const unsigned key =
                            ((cmask[k] >> lane) & 1u) ? 0u : __float_as_uint(v);
                        w[k] = ((u64)key << 32) | (unsigned)~(unsigned)(k * 32 + lane);
                    }
                    u64 lq = pairmax(pairmax(pairmax(w[0], w[1]), pairmax(w[2], w[3])),
                                     pairmax(pairmax(w[4], w[5]), pairmax(w[6], w[7])));
                    const unsigned kk = (unsigned)(lq >> 32);
                    const unsigned cc = (~(unsigned)lq) & 255u;
                    const unsigned mm = __reduce_max_sync(FULL, kk);
                    const unsigned pc = __reduce_min_sync(FULL, (kk == mm) ? cc : FULL);
                    if (lane == src) {
                        const u64 nh = ((u64)mm << 16) |
                            (u64)((~(unsigned)((row << 8) | (int)pc)) & 0xFFFFu);
                        #pragma unroll
                        for (int j = 0; j < 8; j++) if (j == jd) h[j] = nh;
                    }
                }
            }
        }
    } else {
        // ---------- warps 1-7: zero-fill output, overlapped with the loop ----------
        const int zi = tid - 32;                  // 0..223
        float4* o4 = (float4*)obase;
        const float4 z4 = make_float4(0.f, 0.f, 0.f, 0.f);
        #pragma unroll 1
        for (int i = zi; i < NN * NN / 4; i += 224) o4[i] = z4;
    }

    __syncthreads();   // orders zero STGs before the ones; s_perm visible

    // ---------- one-hot: thread tid owns row tid ----------
    obase[(size_t)tid * NN + s_perm[tid]] = 1.0f;
}

extern "C" void kernel_launch(void* const* d_in, const int* in_sizes, int n_in,
                              void* d_out, int out_size) {
    const float* soft = (const float*)d_in[0];
    float* out = (float*)d_out;
    greedy_perm_kernel<<<256, 256>>>(soft, out);
}